// round 14
// baseline (speedup 1.0000x reference)
#include <cuda_runtime.h>
#include <cuda_fp16.h>
#include <math.h>
#include <stdint.h>

#define BSZ  4
#define SEQ  4096
#define DM   1024
#define FF   256
#define ROWS (BSZ*SEQ)            /* 16384 */
#define TAPS 32
#define LN_EPS 1e-5f

// ---------------- scratch (device globals: no alloc allowed) ----------------
__device__ float g_h2    [(size_t)ROWS*DM];     // fp32 GEMM4 out
__device__ __half g_spech[(size_t)ROWS*2*FF];   // fp16 GEMM1 out (conv input)
__device__ __half g_xh[(size_t)ROWS*DM];
__device__ __half g_yh[(size_t)ROWS*2*FF];
__device__ __half g_ch[(size_t)ROWS*DM];
__device__ __half g_hh[(size_t)ROWS*DM];
__device__ __half g_wsh[2*FF*DM];
__device__ __half g_wfh[DM*2*FF];
__device__ __half g_w1h[DM*DM];
__device__ __half g_w2h[DM*DM];
__device__ float g_w[2*TAPS*FF];
__device__ float g_errpart[1024];

// ---------------- PTX helpers ----------------
__device__ __forceinline__ uint32_t smem_u32(const void* p){
    uint32_t a; asm("{ .reg .u64 t; cvta.to.shared.u64 t, %1; cvt.u32.u64 %0, t; }":"=r"(a):"l"(p)); return a;
}
#define CPA16(dst,src) asm volatile("cp.async.cg.shared.global [%0],[%1],16;"::"r"(dst),"l"(src))
#define CPA_COMMIT()   asm volatile("cp.async.commit_group;":::"memory")
#define CPA_WAIT1()    asm volatile("cp.async.wait_group 1;":::"memory")
#define CPA_WAIT0()    asm volatile("cp.async.wait_group 0;":::"memory")

#define LDSM_X4(r0,r1,r2,r3,addr) \
    asm volatile("ldmatrix.sync.aligned.m8n8.x4.shared.b16 {%0,%1,%2,%3},[%4];" \
        : "=r"(r0),"=r"(r1),"=r"(r2),"=r"(r3) : "r"(addr))

#define MMA_F32(d,a,b) \
    asm volatile("mma.sync.aligned.m16n8k16.row.col.f32.f16.f16.f32 " \
        "{%0,%1,%2,%3},{%4,%5,%6,%7},{%8,%9},{%0,%1,%2,%3};" \
        : "+f"((d)[0]),"+f"((d)[1]),"+f"((d)[2]),"+f"((d)[3]) \
        : "r"((a)[0]),"r"((a)[1]),"r"((a)[2]),"r"((a)[3]),"r"((b)[0]),"r"((b)[1]))

// ---------------- block reduce ----------------
template<int WARPS>
__device__ __forceinline__ float block_sum(float v, float* red) {
    #pragma unroll
    for (int o = 16; o > 0; o >>= 1) v += __shfl_xor_sync(0xffffffffu, v, o);
    int lane = threadIdx.x & 31, w = threadIdx.x >> 5;
    if (lane == 0) red[w] = v;
    __syncthreads();
    if (w == 0) {
        float r = (lane < WARPS) ? red[lane] : 0.f;
        #pragma unroll
        for (int o = 16; o > 0; o >>= 1) r += __shfl_xor_sync(0xffffffffu, r, o);
        if (lane == 0) red[0] = r;
    }
    __syncthreads();
    float out = red[0];
    __syncthreads();
    return out;
}

// ---------------- FIR tap precompute ----------------
__global__ void prep_kernel(const float* __restrict__ log_decay,
                            const float* __restrict__ freq) {
    int f = threadIdx.x;
    float decay = 1.f / (1.f + expf(-log_decay[f]));
    float omega = tanhf(freq[f]) * 0.1f;
    float cr = cosf(omega), ci = sinf(omega);
    float Ar = decay * cr, Ai = decay * ci;
    float pr = 1.f, pi = 0.f;
    #pragma unroll 1
    for (int t = 0; t < TAPS; t++) {
        g_w[t*FF + f]           = pr*cr - pi*ci;
        g_w[TAPS*FF + t*FF + f] = pr*ci + pi*cr;
        float nr = pr*Ar - pi*Ai, ni = pr*Ai + pi*Ar;
        pr = nr; pi = ni;
    }
}

// ---------------- all-weights to fp16 (single launch) ----------------------
#define NW1 (2*FF*DM)            /* 524288  */
#define NW2 (DM*2*FF)            /* 524288  */
#define NW3 (DM*DM)              /* 1048576 */
#define NW4 (DM*DM)              /* 1048576 */
__global__ void wsplit_all_kernel(const float* __restrict__ ws, const float* __restrict__ wf,
                                  const float* __restrict__ w1, const float* __restrict__ w2){
    int i = blockIdx.x*256 + threadIdx.x;
    if (i < NW1)                      g_wsh[i]                 = __float2half(ws[i]);
    else if (i < NW1+NW2)             g_wfh[i-NW1]             = __float2half(wf[i-NW1]);
    else if (i < NW1+NW2+NW3)         g_w1h[i-NW1-NW2]         = __float2half(w1[i-NW1-NW2]);
    else if (i < NW1+NW2+NW3+NW4)     g_w2h[i-NW1-NW2-NW3]     = __float2half(w2[i-NW1-NW2-NW3]);
}

// ---------------- LayerNorm over D=1024 ----------------
template<bool TOH>
__global__ void ln_kernel(const float* __restrict__ x, const float* __restrict__ g,
                          const float* __restrict__ b, float* __restrict__ outf,
                          __half* __restrict__ oh) {
    __shared__ float red[8];
    int row = blockIdx.x, tid = threadIdx.x;
    float4 v = ((const float4*)(x + (size_t)row*DM))[tid];
    float mu = block_sum<8>(v.x + v.y + v.z + v.w, red) * (1.f/DM);
    float dx = v.x - mu, dy = v.y - mu, dz = v.z - mu, dw = v.w - mu;
    float var = block_sum<8>(dx*dx + dy*dy + dz*dz + dw*dw, red) * (1.f/DM);
    float rs = rsqrtf(var + LN_EPS);
    float4 gv = ((const float4*)g)[tid];
    float4 bv = ((const float4*)b)[tid];
    float o0 = dx*rs*gv.x + bv.x, o1 = dy*rs*gv.y + bv.y;
    float o2 = dz*rs*gv.z + bv.z, o3 = dw*rs*gv.w + bv.w;
    if (TOH) {
        size_t base = (size_t)row*DM + tid*4;
        ((__half2*)(oh+base))[0] = __halves2half2(__float2half(o0), __float2half(o1));
        ((__half2*)(oh+base))[1] = __halves2half2(__float2half(o2), __float2half(o3));
    } else {
        ((float4*)(outf + (size_t)row*DM))[tid] = make_float4(o0,o1,o2,o3);
    }
}

// ---------------- HMMA fp16 GEMM: C[M,N] = A[M,K] * B[N,K]^T ---------------
// single pass, fp16 operands, f32 accum.
// tile 128x128x64, 256 threads, 8 warps, warp tile 64x32.
// 3-stage cp.async pipeline, ONE __syncthreads per chunk, 2 CTAs/SM.
#define ROWB 144u              /* 128B data + 16B pad; 9 mod 8 = 1 rotation */
#define TILEB (128u*ROWB)      /* 18432 */
#define STAGE (2u*TILEB)       /* 36864: Ah, Bh */
#define NSTG  3                /* 110592 B per CTA -> 2 CTAs/SM */

template<bool BIAS, bool GELU, bool SPLIT, bool ERR>
__global__ void __launch_bounds__(256, 2) gemm_mma(
    const __half* __restrict__ Ah,
    const __half* __restrict__ Bh,
    const float* __restrict__ bias,
    float* __restrict__ Cf, __half* __restrict__ Ch,
    const float* __restrict__ td, const float* __restrict__ ew,
    int M, int N, int K)
{
    extern __shared__ char dsm[];
    __shared__ float red[8];
    const uint32_t sb = smem_u32(dsm);
    const uint32_t OAH = 0, OBH = TILEB;

    const int m0 = blockIdx.y * 128, n0 = blockIdx.x * 128;
    const int tid = threadIdx.x, lane = tid & 31, wid = tid >> 5;
    const int wm0 = (wid & 1) * 64, wn0 = (wid >> 1) * 32;
    const int NC = K >> 6;                 // 64-K chunks

    float acc[4][4][4];
    #pragma unroll
    for (int i = 0; i < 4; i++)
        #pragma unroll
        for (int j = 0; j < 4; j++)
            #pragma unroll
            for (int r = 0; r < 4; r++) acc[i][j][r] = 0.f;

    // cp.async: 128 rows x 8 granules(16B) per tile; 256 thr -> 4 row groups
    const int lr = tid >> 3, lg = tid & 7;

    auto load_stage = [&](int slot, int c){
        uint32_t s0 = sb + (uint32_t)slot*STAGE;
        size_t gb = (size_t)c * 128;       // 64 halfs = 128 bytes
        #pragma unroll
        for (int l = 0; l < 4; l++) {
            int r = lr + l*32;
            uint32_t d = s0 + (uint32_t)r*ROWB + (uint32_t)lg*16u;
            CPA16(d + OAH, (const char*)(Ah + (size_t)(m0 + r)*K + lg*8) + gb);
            CPA16(d + OBH, (const char*)(Bh + (size_t)(n0 + r)*K + lg*8) + gb);
        }
        CPA_COMMIT();
    };

    const uint32_t a_row = (uint32_t)(wm0 + (lane & 15));
    const uint32_t a_kg  = (uint32_t)(lane >> 4);
    const uint32_t b_sel = (uint32_t)(lane >> 3);
    const uint32_t b_row = (uint32_t)(wn0 + ((b_sel >> 1) << 3) + (lane & 7));
    const uint32_t b_kg  = b_sel & 1u;

    load_stage(0, 0);
    load_stage(1, 1);
    int cs = 0, ls = 2;
    for (int c = 0; c < NC; c++) {
        if (c < NC - 1) CPA_WAIT1(); else CPA_WAIT0();
        __syncthreads();                   // all warps done with chunk c-1
        if (c + 2 < NC) {                  // slot ls == (c-1)%3, now free
            load_stage(ls, c + 2);
            ls = (ls == 2) ? 0 : ls + 1;
        }
        uint32_t s0 = sb + (uint32_t)cs*STAGE;
        cs = (cs == 2) ? 0 : cs + 1;

        #pragma unroll
        for (int s = 0; s < 4; s++) {      // four k16 steps per chunk
            uint32_t ah[4][4], bh[4][2];
            #pragma unroll
            for (int mi = 0; mi < 4; mi++) {
                uint32_t ad = s0 + (a_row + mi*16u)*ROWB + ((uint32_t)s*2u + a_kg)*16u;
                LDSM_X4(ah[mi][0], ah[mi][1], ah[mi][2], ah[mi][3], ad + OAH);
            }
            #pragma unroll
            for (int nj = 0; nj < 4; nj += 2) {
                uint32_t bd = s0 + (b_row + (uint32_t)nj*8u)*ROWB + ((uint32_t)s*2u + b_kg)*16u;
                LDSM_X4(bh[nj][0], bh[nj][1], bh[nj+1][0], bh[nj+1][1], bd + OBH);
            }
            #pragma unroll
            for (int mi = 0; mi < 4; mi++)
                #pragma unroll
                for (int ni = 0; ni < 4; ni++)
                    MMA_F32(acc[mi][ni], ah[mi], bh[ni]);
        }
    }

    float sw = 0.f;
    if (ERR) sw = 1.f / (1.f + expf(-ew[0]));
    float esum = 0.f;

    const int er = lane >> 2, ec = (lane & 3) * 2;
    #pragma unroll
    for (int mi = 0; mi < 4; mi++) {
        #pragma unroll
        for (int half = 0; half < 2; half++) {
            int m = m0 + wm0 + mi*16 + er + half*8;
            #pragma unroll
            for (int ni = 0; ni < 4; ni++) {
                int n = n0 + wn0 + ni*8 + ec;
                float v0 = acc[mi][ni][half*2 + 0];
                float v1 = acc[mi][ni][half*2 + 1];
                if (BIAS) { v0 += __ldg(&bias[n]); v1 += __ldg(&bias[n+1]); }
                if (GELU) {
                    v0 = 0.5f * v0 * (1.f + erff(v0 * 0.70710678118654752f));
                    v1 = 0.5f * v1 * (1.f + erff(v1 * 0.70710678118654752f));
                }
                if (ERR) {
                    float2 t = *(const float2*)(td + (size_t)m*N + n);
                    float e0 = fminf(fmaxf(v0 - t.x, -1.f), 1.f);
                    float e1 = fminf(fmaxf(v1 - t.y, -1.f), 1.f);
                    esum += e0*e0 + e1*e1;
                    v0 -= sw*e0; v1 -= sw*e1;
                }
                if (ERR || !SPLIT)
                    *(float2*)(Cf + (size_t)m*N + n) = make_float2(v0, v1);
                if (SPLIT)
                    *(__half2*)(Ch + (size_t)m*N + n) =
                        __halves2half2(__float2half(v0), __float2half(v1));
            }
        }
    }
    if (ERR) {
        float s = block_sum<8>(esum, red);
        if (tid == 0) g_errpart[blockIdx.y * gridDim.x + blockIdx.x] = s;
    }
}

// ---------------- 32-tap complex causal FIR along S (fp16 in / fp16 out) ---
__global__ void __launch_bounds__(256) conv_kernel(
    const __half* __restrict__ u, __half* __restrict__ yh) {
    __shared__ float sur[63*32], sui[63*32];
    __shared__ float swr[TAPS*32], swi[TAPS*32];
    const int f0 = blockIdx.x * 32;
    const int t0 = blockIdx.y * 32;
    const int b  = blockIdx.z;
    const int tid = threadIdx.x;

    for (int i = tid; i < 63*32; i += 256) {
        int tt = i >> 5, fl = i & 31;
        int tg = t0 - 31 + tt;
        float vr = 0.f, vi = 0.f;
        if (tg >= 0) {
            size_t base = ((size_t)(b*SEQ + tg))*(2*FF) + f0 + fl;
            vr = __half2float(u[base]); vi = __half2float(u[base + FF]);
        }
        sur[i] = vr; sui[i] = vi;
    }
    for (int i = tid; i < TAPS*32; i += 256) {
        int tt = i >> 5, fl = i & 31;
        swr[i] = g_w[tt*FF + f0 + fl];
        swi[i] = g_w[TAPS*FF + tt*FF + f0 + fl];
    }
    __syncthreads();

    const int fl = tid & 31, tr = tid >> 5;
    #pragma unroll
    for (int j = 0; j < 4; j++) {
        int tl = tr*4 + j;
        float ar = 0.f, ai = 0.f;
        #pragma unroll
        for (int t = 0; t < TAPS; t++) {
            int idx = (31 + tl - t)*32 + fl;
            float ur = sur[idx], ui = sui[idx];
            float wr = swr[t*32 + fl], wi = swi[t*32 + fl];
            ar += ur*wr - ui*wi;
            ai += ur*wi + ui*wr;
        }
        size_t ob = ((size_t)(b*SEQ + t0 + tl))*(2*FF) + f0 + fl;
        yh[ob]      = __float2half(ar);
        yh[ob + FF] = __float2half(ai);
    }
}

__global__ void fin_kernel(float* __restrict__ out_scalar) {
    __shared__ float red[8];
    float s = 0.f;
    for (int i = threadIdx.x; i < 1024; i += 256) s += g_errpart[i];
    s = block_sum<8>(s, red);
    if (threadIdx.x == 0) {
        float pe = s / (float)((size_t)ROWS * DM);
        out_scalar[0] = fminf(fmaxf(pe, 0.f), 1.f);
    }
}

// ---------------- launch ----------------
extern "C" void kernel_launch(void* const* d_in, const int* in_sizes, int n_in,
                              void* d_out, int out_size) {
    const float* bu    = (const float*)d_in[0];
    const float* td    = (const float*)d_in[1];
    const float* Wspec = (const float*)d_in[2];
    const float* ldec  = (const float*)d_in[3];
    const float* freq  = (const float*)d_in[4];
    const float* Wfrom = (const float*)d_in[5];
    const float* l1g   = (const float*)d_in[6];
    const float* l1b   = (const float*)d_in[7];
    const float* W1    = (const float*)d_in[8];
    const float* b1    = (const float*)d_in[9];
    const float* W2    = (const float*)d_in[10];
    const float* b2    = (const float*)d_in[11];
    const float* l2g   = (const float*)d_in[12];
    const float* l2b   = (const float*)d_in[13];
    const float* ew    = (const float*)d_in[14];

    float* out       = (float*)d_out;
    float* corrected = out;
    float* nextpred  = out + (size_t)ROWS*DM;
    float* pe        = out + 2*(size_t)ROWS*DM;

    float *h2;
    __half *spech,*xh,*yh,*ch,*hh;
    __half *wsh,*wfh,*w1h,*w2h;
    cudaGetSymbolAddress((void**)&h2,     g_h2);
    cudaGetSymbolAddress((void**)&spech,  g_spech);
    cudaGetSymbolAddress((void**)&xh, g_xh);
    cudaGetSymbolAddress((void**)&yh, g_yh);
    cudaGetSymbolAddress((void**)&ch, g_ch);
    cudaGetSymbolAddress((void**)&hh, g_hh);
    cudaGetSymbolAddress((void**)&wsh, g_wsh);
    cudaGetSymbolAddress((void**)&wfh, g_wfh);
    cudaGetSymbolAddress((void**)&w1h, g_w1h);
    cudaGetSymbolAddress((void**)&w2h, g_w2h);

    const int SMEM_BYTES = NSTG * (int)STAGE;   // 110592
    cudaFuncSetAttribute(gemm_mma<false,false,true ,false>, cudaFuncAttributeMaxDynamicSharedMemorySize, SMEM_BYTES);
    cudaFuncSetAttribute(gemm_mma<false,false,true ,true >, cudaFuncAttributeMaxDynamicSharedMemorySize, SMEM_BYTES);
    cudaFuncSetAttribute(gemm_mma<true ,true ,true ,false>, cudaFuncAttributeMaxDynamicSharedMemorySize, SMEM_BYTES);
    cudaFuncSetAttribute(gemm_mma<true ,false,false,false>, cudaFuncAttributeMaxDynamicSharedMemorySize, SMEM_BYTES);

    prep_kernel<<<1, 256>>>(ldec, freq);
    wsplit_all_kernel<<<(NW1+NW2+NW3+NW4+255)/256, 256>>>(Wspec, Wfrom, W1, W2);

    ln_kernel<true><<<ROWS, 256>>>(bu, l1g, l1b, nullptr, xh);

    // GEMM1 writes fp16 spec directly (SPLIT=true, no fp32 out)
    gemm_mma<false,false,true,false><<<dim3((2*FF)/128, ROWS/128), 256, SMEM_BYTES>>>(
        xh, wsh, nullptr, nullptr, spech, nullptr, nullptr, ROWS, 2*FF, DM);

    conv_kernel<<<dim3(FF/32, SEQ/32, BSZ), 256>>>(spech, yh);

    // GEMM2 fused with error/corrected/to-fp16 + per-block error sums
    gemm_mma<false,false,true,true><<<dim3(DM/128, ROWS/128), 256, SMEM_BYTES>>>(
        yh, wfh, nullptr, corrected, ch, td, ew, ROWS, DM, 2*FF);

    fin_kernel<<<1, 256>>>(pe);

    gemm_mma<true,true,true,false><<<dim3(DM/128, ROWS/128), 256, SMEM_BYTES>>>(
        ch, w1h, b1, nullptr, hh, nullptr, nullptr, ROWS, DM, DM);

    gemm_mma<true,false,false,false><<<dim3(DM/128, ROWS/128), 256, SMEM_BYTES>>>(
        hh, w2h, b2, h2, nullptr, nullptr, nullptr, ROWS, DM, DM);

    ln_kernel<false><<<ROWS, 256>>>(h2, l2g, l2b, nextpred, nullptr);
}

// round 15
// speedup vs baseline: 1.0561x; 1.0561x over previous
#include <cuda_runtime.h>
#include <cuda_fp16.h>
#include <math.h>
#include <stdint.h>

#define BSZ  4
#define SEQ  4096
#define DM   1024
#define FF   256
#define ROWS (BSZ*SEQ)            /* 16384 */
#define TAPS 16
#define HALO 15
#define LN_EPS 1e-5f

// ---------------- scratch (device globals: no alloc allowed) ----------------
__device__ __half g_spech[(size_t)ROWS*2*FF];   // fp16 GEMM1 out (conv input)
__device__ __half g_xh[(size_t)ROWS*DM];
__device__ __half g_yh[(size_t)ROWS*2*FF];
__device__ __half g_ch[(size_t)ROWS*DM];
__device__ __half g_hh[(size_t)ROWS*DM];
__device__ __half g_h2h[(size_t)ROWS*DM];       // fp16 GEMM4 out
__device__ __half g_wsh[2*FF*DM];
__device__ __half g_wfh[DM*2*FF];
__device__ __half g_w1h[DM*DM];
__device__ __half g_w2h[DM*DM];
__device__ float g_w[2*TAPS*FF];
__device__ float g_errpart[1024];

// ---------------- PTX helpers ----------------
__device__ __forceinline__ uint32_t smem_u32(const void* p){
    uint32_t a; asm("{ .reg .u64 t; cvta.to.shared.u64 t, %1; cvt.u32.u64 %0, t; }":"=r"(a):"l"(p)); return a;
}
#define CPA16(dst,src) asm volatile("cp.async.cg.shared.global [%0],[%1],16;"::"r"(dst),"l"(src))
#define CPA_COMMIT()   asm volatile("cp.async.commit_group;":::"memory")
#define CPA_WAIT1()    asm volatile("cp.async.wait_group 1;":::"memory")
#define CPA_WAIT0()    asm volatile("cp.async.wait_group 0;":::"memory")

#define LDSM_X4(r0,r1,r2,r3,addr) \
    asm volatile("ldmatrix.sync.aligned.m8n8.x4.shared.b16 {%0,%1,%2,%3},[%4];" \
        : "=r"(r0),"=r"(r1),"=r"(r2),"=r"(r3) : "r"(addr))

#define MMA_F32(d,a,b) \
    asm volatile("mma.sync.aligned.m16n8k16.row.col.f32.f16.f16.f32 " \
        "{%0,%1,%2,%3},{%4,%5,%6,%7},{%8,%9},{%0,%1,%2,%3};" \
        : "+f"((d)[0]),"+f"((d)[1]),"+f"((d)[2]),"+f"((d)[3]) \
        : "r"((a)[0]),"r"((a)[1]),"r"((a)[2]),"r"((a)[3]),"r"((b)[0]),"r"((b)[1]))

// ---------------- block reduce ----------------
template<int WARPS>
__device__ __forceinline__ float block_sum(float v, float* red) {
    #pragma unroll
    for (int o = 16; o > 0; o >>= 1) v += __shfl_xor_sync(0xffffffffu, v, o);
    int lane = threadIdx.x & 31, w = threadIdx.x >> 5;
    if (lane == 0) red[w] = v;
    __syncthreads();
    if (w == 0) {
        float r = (lane < WARPS) ? red[lane] : 0.f;
        #pragma unroll
        for (int o = 16; o > 0; o >>= 1) r += __shfl_xor_sync(0xffffffffu, r, o);
        if (lane == 0) red[0] = r;
    }
    __syncthreads();
    float out = red[0];
    __syncthreads();
    return out;
}

// ---------------- FIR tap precompute ----------------
__global__ void prep_kernel(const float* __restrict__ log_decay,
                            const float* __restrict__ freq) {
    int f = threadIdx.x;
    float decay = 1.f / (1.f + expf(-log_decay[f]));
    float omega = tanhf(freq[f]) * 0.1f;
    float cr = cosf(omega), ci = sinf(omega);
    float Ar = decay * cr, Ai = decay * ci;
    float pr = 1.f, pi = 0.f;
    #pragma unroll 1
    for (int t = 0; t < TAPS; t++) {
        g_w[t*FF + f]           = pr*cr - pi*ci;
        g_w[TAPS*FF + t*FF + f] = pr*ci + pi*cr;
        float nr = pr*Ar - pi*Ai, ni = pr*Ai + pi*Ar;
        pr = nr; pi = ni;
    }
}

// ---------------- all-weights to fp16 (single launch) ----------------------
#define NW1 (2*FF*DM)            /* 524288  */
#define NW2 (DM*2*FF)            /* 524288  */
#define NW3 (DM*DM)              /* 1048576 */
#define NW4 (DM*DM)              /* 1048576 */
__global__ void wsplit_all_kernel(const float* __restrict__ ws, const float* __restrict__ wf,
                                  const float* __restrict__ w1, const float* __restrict__ w2){
    int i = blockIdx.x*256 + threadIdx.x;
    if (i < NW1)                      g_wsh[i]                 = __float2half(ws[i]);
    else if (i < NW1+NW2)             g_wfh[i-NW1]             = __float2half(wf[i-NW1]);
    else if (i < NW1+NW2+NW3)         g_w1h[i-NW1-NW2]         = __float2half(w1[i-NW1-NW2]);
    else if (i < NW1+NW2+NW3+NW4)     g_w2h[i-NW1-NW2-NW3]     = __float2half(w2[i-NW1-NW2-NW3]);
}

// ---------------- LayerNorm over D=1024 ----------------
// INH: input fp16; TOH: output fp16
template<bool INH, bool TOH>
__global__ void ln_kernel(const float* __restrict__ x, const __half* __restrict__ xhalf,
                          const float* __restrict__ g, const float* __restrict__ b,
                          float* __restrict__ outf, __half* __restrict__ oh) {
    __shared__ float red[8];
    int row = blockIdx.x, tid = threadIdx.x;
    float v0, v1, v2, v3;
    if (INH) {
        __half2 p0 = ((const __half2*)(xhalf + (size_t)row*DM))[tid*2];
        __half2 p1 = ((const __half2*)(xhalf + (size_t)row*DM))[tid*2+1];
        float2 f0 = __half22float2(p0), f1 = __half22float2(p1);
        v0 = f0.x; v1 = f0.y; v2 = f1.x; v3 = f1.y;
    } else {
        float4 v = ((const float4*)(x + (size_t)row*DM))[tid];
        v0 = v.x; v1 = v.y; v2 = v.z; v3 = v.w;
    }
    float mu = block_sum<8>(v0 + v1 + v2 + v3, red) * (1.f/DM);
    float dx = v0 - mu, dy = v1 - mu, dz = v2 - mu, dw = v3 - mu;
    float var = block_sum<8>(dx*dx + dy*dy + dz*dz + dw*dw, red) * (1.f/DM);
    float rs = rsqrtf(var + LN_EPS);
    float4 gv = ((const float4*)g)[tid];
    float4 bv = ((const float4*)b)[tid];
    float o0 = dx*rs*gv.x + bv.x, o1 = dy*rs*gv.y + bv.y;
    float o2 = dz*rs*gv.z + bv.z, o3 = dw*rs*gv.w + bv.w;
    if (TOH) {
        size_t base = (size_t)row*DM + tid*4;
        ((__half2*)(oh+base))[0] = __halves2half2(__float2half(o0), __float2half(o1));
        ((__half2*)(oh+base))[1] = __halves2half2(__float2half(o2), __float2half(o3));
    } else {
        ((float4*)(outf + (size_t)row*DM))[tid] = make_float4(o0,o1,o2,o3);
    }
}

// ---------------- HMMA fp16 GEMM: C[M,N] = A[M,K] * B[N,K]^T ---------------
// single pass, fp16 operands, f32 accum.
// tile 128x128x64, 256 threads, 8 warps, warp tile 64x32.
// 3-stage cp.async pipeline, ONE __syncthreads per chunk, 2 CTAs/SM.
#define ROWB 144u              /* 128B data + 16B pad; 9 mod 8 = 1 rotation */
#define TILEB (128u*ROWB)      /* 18432 */
#define STAGE (2u*TILEB)       /* 36864: Ah, Bh */
#define NSTG  3                /* 110592 B per CTA -> 2 CTAs/SM */

template<bool BIAS, bool GELU, bool SPLIT, bool ERR>
__global__ void __launch_bounds__(256, 2) gemm_mma(
    const __half* __restrict__ Ah,
    const __half* __restrict__ Bh,
    const float* __restrict__ bias,
    float* __restrict__ Cf, __half* __restrict__ Ch,
    const float* __restrict__ td, const float* __restrict__ ew,
    int M, int N, int K)
{
    extern __shared__ char dsm[];
    __shared__ float red[8];
    const uint32_t sb = smem_u32(dsm);
    const uint32_t OAH = 0, OBH = TILEB;

    const int m0 = blockIdx.y * 128, n0 = blockIdx.x * 128;
    const int tid = threadIdx.x, lane = tid & 31, wid = tid >> 5;
    const int wm0 = (wid & 1) * 64, wn0 = (wid >> 1) * 32;
    const int NC = K >> 6;                 // 64-K chunks

    float acc[4][4][4];
    #pragma unroll
    for (int i = 0; i < 4; i++)
        #pragma unroll
        for (int j = 0; j < 4; j++)
            #pragma unroll
            for (int r = 0; r < 4; r++) acc[i][j][r] = 0.f;

    // cp.async: 128 rows x 8 granules(16B) per tile; 256 thr -> 4 row groups
    const int lr = tid >> 3, lg = tid & 7;

    auto load_stage = [&](int slot, int c){
        uint32_t s0 = sb + (uint32_t)slot*STAGE;
        size_t gb = (size_t)c * 128;       // 64 halfs = 128 bytes
        #pragma unroll
        for (int l = 0; l < 4; l++) {
            int r = lr + l*32;
            uint32_t d = s0 + (uint32_t)r*ROWB + (uint32_t)lg*16u;
            CPA16(d + OAH, (const char*)(Ah + (size_t)(m0 + r)*K + lg*8) + gb);
            CPA16(d + OBH, (const char*)(Bh + (size_t)(n0 + r)*K + lg*8) + gb);
        }
        CPA_COMMIT();
    };

    const uint32_t a_row = (uint32_t)(wm0 + (lane & 15));
    const uint32_t a_kg  = (uint32_t)(lane >> 4);
    const uint32_t b_sel = (uint32_t)(lane >> 3);
    const uint32_t b_row = (uint32_t)(wn0 + ((b_sel >> 1) << 3) + (lane & 7));
    const uint32_t b_kg  = b_sel & 1u;

    load_stage(0, 0);
    load_stage(1, 1);
    int cs = 0, ls = 2;
    for (int c = 0; c < NC; c++) {
        if (c < NC - 1) CPA_WAIT1(); else CPA_WAIT0();
        __syncthreads();                   // all warps done with chunk c-1
        if (c + 2 < NC) {                  // slot ls == (c-1)%3, now free
            load_stage(ls, c + 2);
            ls = (ls == 2) ? 0 : ls + 1;
        }
        uint32_t s0 = sb + (uint32_t)cs*STAGE;
        cs = (cs == 2) ? 0 : cs + 1;

        #pragma unroll
        for (int s = 0; s < 4; s++) {      // four k16 steps per chunk
            uint32_t ah[4][4], bh[4][2];
            #pragma unroll
            for (int mi = 0; mi < 4; mi++) {
                uint32_t ad = s0 + (a_row + mi*16u)*ROWB + ((uint32_t)s*2u + a_kg)*16u;
                LDSM_X4(ah[mi][0], ah[mi][1], ah[mi][2], ah[mi][3], ad + OAH);
            }
            #pragma unroll
            for (int nj = 0; nj < 4; nj += 2) {
                uint32_t bd = s0 + (b_row + (uint32_t)nj*8u)*ROWB + ((uint32_t)s*2u + b_kg)*16u;
                LDSM_X4(bh[nj][0], bh[nj][1], bh[nj+1][0], bh[nj+1][1], bd + OBH);
            }
            #pragma unroll
            for (int mi = 0; mi < 4; mi++)
                #pragma unroll
                for (int ni = 0; ni < 4; ni++)
                    MMA_F32(acc[mi][ni], ah[mi], bh[ni]);
        }
    }

    float sw = 0.f;
    if (ERR) sw = 1.f / (1.f + expf(-ew[0]));
    float esum = 0.f;

    const int er = lane >> 2, ec = (lane & 3) * 2;
    #pragma unroll
    for (int mi = 0; mi < 4; mi++) {
        #pragma unroll
        for (int half = 0; half < 2; half++) {
            int m = m0 + wm0 + mi*16 + er + half*8;
            #pragma unroll
            for (int ni = 0; ni < 4; ni++) {
                int n = n0 + wn0 + ni*8 + ec;
                float v0 = acc[mi][ni][half*2 + 0];
                float v1 = acc[mi][ni][half*2 + 1];
                if (BIAS) { v0 += __ldg(&bias[n]); v1 += __ldg(&bias[n+1]); }
                if (GELU) {
                    v0 = 0.5f * v0 * (1.f + erff(v0 * 0.70710678118654752f));
                    v1 = 0.5f * v1 * (1.f + erff(v1 * 0.70710678118654752f));
                }
                if (ERR) {
                    float2 t = *(const float2*)(td + (size_t)m*N + n);
                    float e0 = fminf(fmaxf(v0 - t.x, -1.f), 1.f);
                    float e1 = fminf(fmaxf(v1 - t.y, -1.f), 1.f);
                    esum += e0*e0 + e1*e1;
                    v0 -= sw*e0; v1 -= sw*e1;
                }
                if (ERR || !SPLIT)
                    *(float2*)(Cf + (size_t)m*N + n) = make_float2(v0, v1);
                if (SPLIT)
                    *(__half2*)(Ch + (size_t)m*N + n) =
                        __halves2half2(__float2half(v0), __float2half(v1));
            }
        }
    }
    if (ERR) {
        float s = block_sum<8>(esum, red);
        if (tid == 0) g_errpart[blockIdx.y * gridDim.x + blockIdx.x] = s;
    }
}

// ---------------- 16-tap complex causal FIR along S (fp16 in / fp16 out) ---
__global__ void __launch_bounds__(256) conv_kernel(
    const __half* __restrict__ u, __half* __restrict__ yh) {
    __shared__ float sur[(32+HALO)*32], sui[(32+HALO)*32];
    __shared__ float swr[TAPS*32], swi[TAPS*32];
    const int f0 = blockIdx.x * 32;
    const int t0 = blockIdx.y * 32;
    const int b  = blockIdx.z;
    const int tid = threadIdx.x;

    for (int i = tid; i < (32+HALO)*32; i += 256) {
        int tt = i >> 5, fl = i & 31;
        int tg = t0 - HALO + tt;
        float vr = 0.f, vi = 0.f;
        if (tg >= 0) {
            size_t base = ((size_t)(b*SEQ + tg))*(2*FF) + f0 + fl;
            vr = __half2float(u[base]); vi = __half2float(u[base + FF]);
        }
        sur[i] = vr; sui[i] = vi;
    }
    for (int i = tid; i < TAPS*32; i += 256) {
        int tt = i >> 5, fl = i & 31;
        swr[i] = g_w[tt*FF + f0 + fl];
        swi[i] = g_w[TAPS*FF + tt*FF + f0 + fl];
    }
    __syncthreads();

    const int fl = tid & 31, tr = tid >> 5;
    #pragma unroll
    for (int j = 0; j < 4; j++) {
        int tl = tr*4 + j;
        float ar = 0.f, ai = 0.f;
        #pragma unroll
        for (int t = 0; t < TAPS; t++) {
            int idx = (HALO + tl - t)*32 + fl;
            float ur = sur[idx], ui = sui[idx];
            float wr = swr[t*32 + fl], wi = swi[t*32 + fl];
            ar += ur*wr - ui*wi;
            ai += ur*wi + ui*wr;
        }
        size_t ob = ((size_t)(b*SEQ + t0 + tl))*(2*FF) + f0 + fl;
        yh[ob]      = __float2half(ar);
        yh[ob + FF] = __float2half(ai);
    }
}

__global__ void fin_kernel(float* __restrict__ out_scalar) {
    __shared__ float red[8];
    float s = 0.f;
    for (int i = threadIdx.x; i < 1024; i += 256) s += g_errpart[i];
    s = block_sum<8>(s, red);
    if (threadIdx.x == 0) {
        float pe = s / (float)((size_t)ROWS * DM);
        out_scalar[0] = fminf(fmaxf(pe, 0.f), 1.f);
    }
}

// ---------------- launch ----------------
extern "C" void kernel_launch(void* const* d_in, const int* in_sizes, int n_in,
                              void* d_out, int out_size) {
    const float* bu    = (const float*)d_in[0];
    const float* td    = (const float*)d_in[1];
    const float* Wspec = (const float*)d_in[2];
    const float* ldec  = (const float*)d_in[3];
    const float* freq  = (const float*)d_in[4];
    const float* Wfrom = (const float*)d_in[5];
    const float* l1g   = (const float*)d_in[6];
    const float* l1b   = (const float*)d_in[7];
    const float* W1    = (const float*)d_in[8];
    const float* b1    = (const float*)d_in[9];
    const float* W2    = (const float*)d_in[10];
    const float* b2    = (const float*)d_in[11];
    const float* l2g   = (const float*)d_in[12];
    const float* l2b   = (const float*)d_in[13];
    const float* ew    = (const float*)d_in[14];

    float* out       = (float*)d_out;
    float* corrected = out;
    float* nextpred  = out + (size_t)ROWS*DM;
    float* pe        = out + 2*(size_t)ROWS*DM;

    __half *spech,*xh,*yh,*ch,*hh,*h2h;
    __half *wsh,*wfh,*w1h,*w2h;
    cudaGetSymbolAddress((void**)&spech,  g_spech);
    cudaGetSymbolAddress((void**)&xh, g_xh);
    cudaGetSymbolAddress((void**)&yh, g_yh);
    cudaGetSymbolAddress((void**)&ch, g_ch);
    cudaGetSymbolAddress((void**)&hh, g_hh);
    cudaGetSymbolAddress((void**)&h2h, g_h2h);
    cudaGetSymbolAddress((void**)&wsh, g_wsh);
    cudaGetSymbolAddress((void**)&wfh, g_wfh);
    cudaGetSymbolAddress((void**)&w1h, g_w1h);
    cudaGetSymbolAddress((void**)&w2h, g_w2h);

    const int SMEM_BYTES = NSTG * (int)STAGE;   // 110592
    cudaFuncSetAttribute(gemm_mma<false,false,true ,false>, cudaFuncAttributeMaxDynamicSharedMemorySize, SMEM_BYTES);
    cudaFuncSetAttribute(gemm_mma<false,false,true ,true >, cudaFuncAttributeMaxDynamicSharedMemorySize, SMEM_BYTES);
    cudaFuncSetAttribute(gemm_mma<true ,true ,true ,false>, cudaFuncAttributeMaxDynamicSharedMemorySize, SMEM_BYTES);
    cudaFuncSetAttribute(gemm_mma<true ,false,true ,false>, cudaFuncAttributeMaxDynamicSharedMemorySize, SMEM_BYTES);

    prep_kernel<<<1, 256>>>(ldec, freq);
    wsplit_all_kernel<<<(NW1+NW2+NW3+NW4+255)/256, 256>>>(Wspec, Wfrom, W1, W2);

    // LN1: fp32 in -> fp16 out
    ln_kernel<false,true><<<ROWS, 256>>>(bu, nullptr, l1g, l1b, nullptr, xh);

    // GEMM1 writes fp16 spec directly
    gemm_mma<false,false,true,false><<<dim3((2*FF)/128, ROWS/128), 256, SMEM_BYTES>>>(
        xh, wsh, nullptr, nullptr, spech, nullptr, nullptr, ROWS, 2*FF, DM);

    conv_kernel<<<dim3(FF/32, SEQ/32, BSZ), 256>>>(spech, yh);

    // GEMM2 fused with error/corrected/to-fp16 + per-block error sums
    gemm_mma<false,false,true,true><<<dim3(DM/128, ROWS/128), 256, SMEM_BYTES>>>(
        yh, wfh, nullptr, corrected, ch, td, ew, ROWS, DM, 2*FF);

    fin_kernel<<<1, 256>>>(pe);

    gemm_mma<true,true,true,false><<<dim3(DM/128, ROWS/128), 256, SMEM_BYTES>>>(
        ch, w1h, b1, nullptr, hh, nullptr, nullptr, ROWS, DM, DM);

    // GEMM4 writes fp16 h2
    gemm_mma<true,false,true,false><<<dim3(DM/128, ROWS/128), 256, SMEM_BYTES>>>(
        hh, w2h, b2, nullptr, h2h, nullptr, nullptr, ROWS, DM, DM);

    // LN2: fp16 in -> fp32 out
    ln_kernel<true,false><<<ROWS, 256>>>(nullptr, h2h, l2g, l2b, nextpred, nullptr);
}